// round 13
// baseline (speedup 1.0000x reference)
#include <cuda_runtime.h>
#include <cstdint>

#define NNODES 50000
#define NEDGES 800000
#define NLBL   100000
#define FIN    128
#define FHID   128
#define FOUT   64

#define CSR_BLOCKS 196   // 196*256 = 50176 >= NNODES; >=2 blocks/SM -> all co-resident

// ---------------- device scratch (static, no runtime allocation) ----------------
__device__ int   g_cnt[NNODES];            // zeroed at module load; re-zeroed inside k_csr each call
__device__ int   g_bsum[CSR_BLOCKS];
__device__ int   g_rowstart[NNODES + 1];   // after fill phase: g_rowstart[v] = END of v's range
__device__ float g_dinv[NNODES];
__device__ int   g_srcs[NEDGES];
__device__ unsigned g_barcnt[3];           // software grid-barrier counters (self-resetting)
__device__ unsigned g_sense[3];            // sense-reversal flags (flip each use; replay-safe)
__device__ __align__(16) float g_hh[(size_t)NNODES * 128];    // GEMM out (raw L1, dinv-scaled L2/L3)
__device__ __align__(16) float g_z[(size_t)NNODES * 128];     // layer activation
__device__ __align__(16) float g_zout[(size_t)NNODES * 64];   // final embeddings

// ---------------- software grid barrier (sense-reversing, replay-safe) ----------------
__device__ __forceinline__ void gbar(int i) {
    __threadfence();            // make this thread's prior stores visible device-wide
    __syncthreads();            // whole block arrived (and fenced)
    if (threadIdx.x == 0) {
        unsigned s = atomicAdd(&g_sense[i], 0u);          // current sense (pre-flip: no one can
                                                          // flip until all blocks arrive)
        unsigned t = atomicAdd(&g_barcnt[i], 1u);
        if (t == CSR_BLOCKS - 1) {
            g_barcnt[i] = 0;                              // reset BEFORE release
            __threadfence();
            atomicExch(&g_sense[i], s ^ 1u);              // release all spinners
        } else {
            while (atomicAdd(&g_sense[i], 0u) == s) { }   // spin (atomic read, L1-bypassing)
        }
    }
    __syncthreads();
}

// ---------------- fused CSR build: count -> scan -> fill, one launch ----------------
__global__ void __launch_bounds__(256, 2)
k_csr(const int* __restrict__ ei, int E, int n) {
    __shared__ int sh[256];
    __shared__ int bs[256];
    __shared__ int ws[8];
    const int NT = CSR_BLOCKS * 256;             // 50176 threads
    int tid  = threadIdx.x;
    int gtid = blockIdx.x * 256 + tid;

    // ---- phase 1: degree count (8 edges per iter, 8 atomic chains in flight) ----
    for (int t = gtid; t * 8 < E; t += NT) {
        const int4* dp = (const int4*)(ei + E);
        int4 d0 = dp[t * 2];
        int4 d1 = dp[t * 2 + 1];
        atomicAdd(&g_cnt[d0.x], 1);
        atomicAdd(&g_cnt[d0.y], 1);
        atomicAdd(&g_cnt[d0.z], 1);
        atomicAdd(&g_cnt[d0.w], 1);
        atomicAdd(&g_cnt[d1.x], 1);
        atomicAdd(&g_cnt[d1.y], 1);
        atomicAdd(&g_cnt[d1.z], 1);
        atomicAdd(&g_cnt[d1.w], 1);
    }
    gbar(0);

    // ---- phase 2: per-block sums (c stays in a register for phase 3) ----
    int c = (gtid < n) ? g_cnt[gtid] : 0;
    if (gtid < n) g_cnt[gtid] = 0;               // re-zero for the next call/replay
    {
        int s = c;
#pragma unroll
        for (int o = 16; o; o >>= 1) s += __shfl_xor_sync(0xffffffffu, s, o);
        if ((tid & 31) == 0) ws[tid >> 5] = s;
        __syncthreads();
        if (tid < 8) {
            int t = ws[tid];
#pragma unroll
            for (int o = 4; o; o >>= 1) t += __shfl_xor_sync(0xffu, t, o);
            if (tid == 0) g_bsum[blockIdx.x] = t;
        }
    }
    gbar(1);

    // ---- phase 3: local scan + per-block scan of block sums -> rowstart, dinv ----
    sh[tid] = c;
    bs[tid] = (tid < CSR_BLOCKS) ? g_bsum[tid] : 0;
    __syncthreads();
    for (int o = 1; o < 256; o <<= 1) {
        int u  = (tid >= o) ? sh[tid - o] : 0;
        int u2 = (tid >= o) ? bs[tid - o] : 0;
        __syncthreads();
        sh[tid] += u;
        bs[tid] += u2;
        __syncthreads();
    }
    int off = (blockIdx.x == 0) ? 0 : bs[blockIdx.x - 1];
    if (gtid < n) {
        g_rowstart[gtid] = off + sh[tid] - c;    // exclusive prefix
        g_dinv[gtid] = rsqrtf((float)c + 1.0f);
    }
    if (gtid == n - 1) g_rowstart[n] = off + sh[tid];
    gbar(2);

    // ---- phase 4: fill (atomically bump rowstart; afterwards rowstart[v] == end(v)) ----
    for (int t = gtid; t * 8 < E; t += NT) {
        const int4* sp = (const int4*)ei;
        const int4* dp = (const int4*)(ei + E);
        int4 s0 = sp[t * 2], s1 = sp[t * 2 + 1];
        int4 d0 = dp[t * 2], d1 = dp[t * 2 + 1];
        int p0 = atomicAdd(&g_rowstart[d0.x], 1);
        int p1 = atomicAdd(&g_rowstart[d0.y], 1);
        int p2 = atomicAdd(&g_rowstart[d0.z], 1);
        int p3 = atomicAdd(&g_rowstart[d0.w], 1);
        int p4 = atomicAdd(&g_rowstart[d1.x], 1);
        int p5 = atomicAdd(&g_rowstart[d1.y], 1);
        int p6 = atomicAdd(&g_rowstart[d1.z], 1);
        int p7 = atomicAdd(&g_rowstart[d1.w], 1);
        g_srcs[p0] = s0.x;
        g_srcs[p1] = s0.y;
        g_srcs[p2] = s0.z;
        g_srcs[p3] = s0.w;
        g_srcs[p4] = s1.x;
        g_srcs[p5] = s1.y;
        g_srcs[p6] = s1.z;
        g_srcs[p7] = s1.w;
    }
}

// ---------------- helpers for tf32 tensor-core GEMM ----------------
__device__ __forceinline__ uint32_t f2tf32(float f) {
    uint32_t r;
    asm("cvt.rna.tf32.f32 %0, %1;" : "=r"(r) : "f"(f));
    return r;
}

__device__ __forceinline__ void mma_tf32(float c[4],
                                         uint32_t a0, uint32_t a1, uint32_t a2, uint32_t a3,
                                         uint32_t b0, uint32_t b1) {
    asm volatile(
        "mma.sync.aligned.m16n8k8.row.col.f32.tf32.tf32.f32 "
        "{%0,%1,%2,%3}, {%4,%5,%6,%7}, {%8,%9}, {%0,%1,%2,%3};"
        : "+f"(c[0]), "+f"(c[1]), "+f"(c[2]), "+f"(c[3])
        : "r"(a0), "r"(a1), "r"(a2), "r"(a3), "r"(b0), "r"(b1));
}

// ---------------- GEMM (tensor core tf32) ----------------
// g_hh[row] = A[row] @ W, optionally scaled by dinv[row] (scaleOut=1 for layers 2/3).
// BM=128, BN=64, BK=32. 256 threads = 8 warps (4m x 2n); warp tile 32x32.
__global__ void __launch_bounds__(256)
k_gemm_tc(const float* __restrict__ Ain, const float* __restrict__ W,
          int N, int Fout, int useZ, int scaleOut) {
    const int K = 128;
    const float* A = useZ ? (const float*)g_z : Ain;

    __shared__ uint32_t As[128][36];   // [m][k], pad 4 -> conflict-free
    __shared__ uint32_t Ws[32][68];    // [k][n], pad 4 -> conflict-free

    int tid  = threadIdx.x;
    int warp = tid >> 5, lane = tid & 31;
    int wm = warp >> 1, wn = warp & 1;
    int rb = blockIdx.x * 128, cb = blockIdx.y * 64;
    int grp = lane >> 2, tg = lane & 3;

    float c[2][4][4] = {};   // [m-frag][n-frag][c0..c3]

    for (int k0 = 0; k0 < K; k0 += 32) {
#pragma unroll
        for (int i = 0; i < 4; i++) {
            int idx = tid + i * 256;
            int row = idx >> 3;
            int cc  = (idx & 7) * 4;
            float4 v = make_float4(0.f, 0.f, 0.f, 0.f);
            if (rb + row < N) v = *(const float4*)(A + (size_t)(rb + row) * K + k0 + cc);
            As[row][cc + 0] = f2tf32(v.x);
            As[row][cc + 1] = f2tf32(v.y);
            As[row][cc + 2] = f2tf32(v.z);
            As[row][cc + 3] = f2tf32(v.w);
        }
#pragma unroll
        for (int i = 0; i < 2; i++) {
            int idx = tid + i * 256;
            int kk = idx >> 4;
            int cc = (idx & 15) * 4;
            float4 v = *(const float4*)(W + (size_t)(k0 + kk) * Fout + cb + cc);
            Ws[kk][cc + 0] = f2tf32(v.x);
            Ws[kk][cc + 1] = f2tf32(v.y);
            Ws[kk][cc + 2] = f2tf32(v.z);
            Ws[kk][cc + 3] = f2tf32(v.w);
        }
        __syncthreads();

#pragma unroll
        for (int ks = 0; ks < 4; ks++) {
            int kb = ks * 8;
            uint32_t a[2][4], b[4][2];
#pragma unroll
            for (int mi = 0; mi < 2; mi++) {
                int r0 = wm * 32 + mi * 16 + grp;
                a[mi][0] = As[r0][kb + tg];
                a[mi][1] = As[r0 + 8][kb + tg];
                a[mi][2] = As[r0][kb + tg + 4];
                a[mi][3] = As[r0 + 8][kb + tg + 4];
            }
#pragma unroll
            for (int ni = 0; ni < 4; ni++) {
                int n0 = wn * 32 + ni * 8 + grp;
                b[ni][0] = Ws[kb + tg][n0];
                b[ni][1] = Ws[kb + tg + 4][n0];
            }
#pragma unroll
            for (int mi = 0; mi < 2; mi++)
#pragma unroll
                for (int ni = 0; ni < 4; ni++)
                    mma_tf32(c[mi][ni], a[mi][0], a[mi][1], a[mi][2], a[mi][3],
                             b[ni][0], b[ni][1]);
        }
        __syncthreads();
    }

#pragma unroll
    for (int mi = 0; mi < 2; mi++) {
#pragma unroll
        for (int half = 0; half < 2; half++) {
            int row = rb + wm * 32 + mi * 16 + grp + half * 8;
            if (row < N) {
                float dv = scaleOut ? __ldg(&g_dinv[row]) : 1.0f;
#pragma unroll
                for (int ni = 0; ni < 4; ni++) {
                    int col = cb + wn * 32 + ni * 8 + tg * 2;
                    float2 o = make_float2(c[mi][ni][half * 2 + 0] * dv,
                                           c[mi][ni][half * 2 + 1] * dv);
                    *(float2*)(g_hh + (size_t)row * Fout + col) = o;
                }
            }
        }
    }
}

// ---------------- Aggregation ----------------
// PRESCALED=0 (layer 1, hh raw):        out[v] = relu?( dinv[v]*(Σ dinv[s]h[s] + dinv[v]h[v]) + b )
// PRESCALED=1 (layers 2/3, hh'=dinv·h): out[v] = relu?( dinv[v]*(Σ hh'[s] + hh'[v]) + b )
// Neighbor range of v is [rowstart[v-1], rowstart[v]) (rowstart holds ENDs after fill).
template <int VEC, int PRESCALED>   // VEC=4 -> F=128, VEC=2 -> F=64
__global__ void k_agg(const float* __restrict__ bias, int N, int F, int relu, int toZ) {
    int warp = (blockIdx.x * blockDim.x + threadIdx.x) >> 5;
    int lane = threadIdx.x & 31;
    if (warp >= N) return;
    int v = warp;
    int fo = lane * VEC;
    const float* __restrict__ hh = g_hh;

    float dvv = __ldg(&g_dinv[v]);
    float selfScale = PRESCALED ? 1.0f : dvv;
    float acc[VEC];
    {
        const float* hv = hh + (size_t)v * F + fo;
        if (VEC == 4) {
            float4 t = *(const float4*)hv;
            acc[0] = t.x * selfScale; acc[1] = t.y * selfScale;
            acc[2] = t.z * selfScale; acc[3] = t.w * selfScale;
        } else {
            float2 t = *(const float2*)hv;
            acc[0] = t.x * selfScale; acc[1] = t.y * selfScale;
        }
    }
    int e1 = __ldg(&g_rowstart[v]);
    int e0 = (v == 0) ? 0 : __ldg(&g_rowstart[v - 1]);

    int i = e0;
    for (; i + 8 <= e1; i += 8) {
        int s[8];
        float dv[8];
#pragma unroll
        for (int j = 0; j < 8; j++) s[j] = __ldg(&g_srcs[i + j]);
        if (!PRESCALED) {
#pragma unroll
            for (int j = 0; j < 8; j++) dv[j] = __ldg(&g_dinv[s[j]]);
        }
#pragma unroll
        for (int j = 0; j < 8; j++) {
            const float* hs = hh + (size_t)s[j] * F + fo;
            if (VEC == 4) {
                float4 t = *(const float4*)hs;
                if (PRESCALED) {
                    acc[0] += t.x; acc[1] += t.y; acc[2] += t.z; acc[3] += t.w;
                } else {
                    acc[0] = fmaf(t.x, dv[j], acc[0]);
                    acc[1] = fmaf(t.y, dv[j], acc[1]);
                    acc[2] = fmaf(t.z, dv[j], acc[2]);
                    acc[3] = fmaf(t.w, dv[j], acc[3]);
                }
            } else {
                float2 t = *(const float2*)hs;
                if (PRESCALED) {
                    acc[0] += t.x; acc[1] += t.y;
                } else {
                    acc[0] = fmaf(t.x, dv[j], acc[0]);
                    acc[1] = fmaf(t.y, dv[j], acc[1]);
                }
            }
        }
    }
    for (; i < e1; i++) {
        int s = __ldg(&g_srcs[i]);
        float dv = PRESCALED ? 1.0f : __ldg(&g_dinv[s]);
        const float* hs = hh + (size_t)s * F + fo;
        if (VEC == 4) {
            float4 t = *(const float4*)hs;
            if (PRESCALED) {
                acc[0] += t.x; acc[1] += t.y; acc[2] += t.z; acc[3] += t.w;
            } else {
                acc[0] = fmaf(t.x, dv, acc[0]);
                acc[1] = fmaf(t.y, dv, acc[1]);
                acc[2] = fmaf(t.z, dv, acc[2]);
                acc[3] = fmaf(t.w, dv, acc[3]);
            }
        } else {
            float2 t = *(const float2*)hs;
            if (PRESCALED) {
                acc[0] += t.x; acc[1] += t.y;
            } else {
                acc[0] = fmaf(t.x, dv, acc[0]);
                acc[1] = fmaf(t.y, dv, acc[1]);
            }
        }
    }

    float o[VEC];
#pragma unroll
    for (int k = 0; k < VEC; k++) {
        float val = fmaf(acc[k], dvv, bias[fo + k]);
        if (relu) val = fmaxf(val, 0.f);
        o[k] = val;
    }
    float* op = (toZ ? g_z : g_zout) + (size_t)v * F + fo;
    if (VEC == 4) *(float4*)op = make_float4(o[0], o[1], o[2], o[3]);
    else          *(float2*)op = make_float2(o[0], o[1]);
}

// ---------------- Decode: out[j] = dot(zout[a], zout[b]) over 64 dims ----------------
__global__ void k_decode(const int* __restrict__ eli, float* __restrict__ out, int L) {
    int warp = (blockIdx.x * blockDim.x + threadIdx.x) >> 5;
    int lane = threadIdx.x & 31;
    if (warp >= L) return;
    int a = eli[warp];
    int b = eli[(size_t)L + warp];
    float2 za = *(const float2*)(g_zout + (size_t)a * 64 + lane * 2);
    float2 zb = *(const float2*)(g_zout + (size_t)b * 64 + lane * 2);
    float p = za.x * zb.x + za.y * zb.y;
#pragma unroll
    for (int off = 16; off > 0; off >>= 1)
        p += __shfl_xor_sync(0xffffffff, p, off);
    if (lane == 0) out[warp] = p;
}

static inline int aggGrid(int nNodes) { return (nNodes * 32 + 255) / 256; }

// ---------------- launch ----------------
extern "C" void kernel_launch(void* const* d_in, const int* in_sizes, int n_in,
                              void* d_out, int out_size) {
    const float* x   = (const float*)d_in[0];
    const int*   ei  = (const int*)d_in[1];    // int32 (JAX x64 disabled)
    const int*   eli = (const int*)d_in[2];
    const float* W1  = (const float*)d_in[3];
    const float* b1  = (const float*)d_in[4];
    const float* W2  = (const float*)d_in[5];
    const float* b2  = (const float*)d_in[6];
    const float* W3  = (const float*)d_in[7];
    const float* b3  = (const float*)d_in[8];
    float* out = (float*)d_out;

    // single side stream + 2 events (round-10 lesson: two streams trip the teardown guard)
    cudaStream_t s2;
    cudaEvent_t ev0, evG1;
    cudaStreamCreateWithFlags(&s2, cudaStreamNonBlocking);
    cudaEventCreateWithFlags(&ev0,  cudaEventDisableTiming);
    cudaEventCreateWithFlags(&evG1, cudaEventDisableTiming);

    // fork: GEMM-1 -> g_hh raw (independent of CSR) runs concurrently with fused CSR build
    cudaEventRecord(ev0, 0);
    cudaStreamWaitEvent(s2, ev0, 0);
    k_gemm_tc<<<dim3((NNODES + 127) / 128, FHID / 64), 256, 0, s2>>>(x, W1, NNODES, FHID, 0, 0);
    cudaEventRecord(evG1, s2);

    // fused CSR build (count -> scan -> fill in ONE launch, software grid barriers)
    k_csr<<<CSR_BLOCKS, 256>>>(ei, NEDGES, NNODES);

    cudaStreamWaitEvent(0, evG1, 0);          // join gemm1

    // ---- layer 1 agg (raw hh) -> z (relu) ----
    k_agg<4, 0><<<aggGrid(NNODES), 256>>>(b1, NNODES, 128, 1, 1);
    // ---- layer 2 (gemm epilogue pre-scales by dinv) ----
    k_gemm_tc<<<dim3((NNODES + 127) / 128, FHID / 64), 256>>>(nullptr, W2, NNODES, FHID, 1, 1);
    k_agg<4, 1><<<aggGrid(NNODES), 256>>>(b2, NNODES, 128, 1, 1);
    // ---- layer 3 (gemm epilogue pre-scales by dinv) ----
    k_gemm_tc<<<dim3((NNODES + 127) / 128, FOUT / 64), 256>>>(nullptr, W3, NNODES, FOUT, 1, 1);
    k_agg<2, 1><<<aggGrid(NNODES), 256>>>(b3, NNODES, 64, 0, 0);
    // ---- decode ----
    k_decode<<<(NLBL * 32 + 255) / 256, 256>>>(eli, out, NLBL);
}

// round 14
// speedup vs baseline: 1.0839x; 1.0839x over previous
#include <cuda_runtime.h>
#include <cstdint>

#define NNODES 50000
#define NEDGES 800000
#define NLBL   100000
#define FIN    128
#define FHID   128
#define FOUT   64

#define SCAN_BLOCKS 196   // 196*256 = 50176 >= NNODES

// ---------------- device scratch (static, no runtime allocation) ----------------
__device__ int   g_cnt[NNODES];            // zero at module load; re-zeroed off-critical-path each call
__device__ int   g_bsum[SCAN_BLOCKS];
__device__ int   g_rowstart[NNODES + 1];   // after k_fill: g_rowstart[v] = END of v's range
__device__ float g_dinv[NNODES];
__device__ int   g_srcs[NEDGES];
__device__ __align__(16) float g_hh[(size_t)NNODES * 128];    // raw GEMM out (h = A @ W)
__device__ __align__(16) float g_z[(size_t)NNODES * 128];     // layer activation
__device__ __align__(16) float g_zout[(size_t)NNODES * 64];   // final embeddings

// ---------------- CSR build ----------------
__global__ void k_zero(int n) {
    int i = blockIdx.x * blockDim.x + threadIdx.x;
    if (i < n) g_cnt[i] = 0;
}

// 8 edges per thread: 8 independent atomic chains in flight
__global__ void k_count(const int* __restrict__ ei, int E) {
    int t = blockIdx.x * blockDim.x + threadIdx.x;
    if (t * 8 >= E) return;
    const int4* dp = (const int4*)(ei + E);
    int4 d0 = dp[t * 2];
    int4 d1 = dp[t * 2 + 1];
    atomicAdd(&g_cnt[d0.x], 1);
    atomicAdd(&g_cnt[d0.y], 1);
    atomicAdd(&g_cnt[d0.z], 1);
    atomicAdd(&g_cnt[d0.w], 1);
    atomicAdd(&g_cnt[d1.x], 1);
    atomicAdd(&g_cnt[d1.y], 1);
    atomicAdd(&g_cnt[d1.z], 1);
    atomicAdd(&g_cnt[d1.w], 1);
}

// ---- two-phase parallel scan over g_cnt ----
__global__ void k_scanA(int n) {    // grid=SCAN_BLOCKS, block=256: block sums
    int tid = threadIdx.x;
    int i = blockIdx.x * 256 + tid;
    int c = (i < n) ? g_cnt[i] : 0;
    __shared__ int ws[8];
    int s = c;
#pragma unroll
    for (int o = 16; o; o >>= 1) s += __shfl_xor_sync(0xffffffffu, s, o);
    if ((tid & 31) == 0) ws[tid >> 5] = s;
    __syncthreads();
    if (tid < 8) {
        int t = ws[tid];
#pragma unroll
        for (int o = 4; o; o >>= 1) t += __shfl_xor_sync(0xffu, t, o);
        if (tid == 0) g_bsum[blockIdx.x] = t;
    }
}

// local scan + redundant per-block scan of the 196 block sums (no separate phase-B launch)
__global__ void k_scanC(int n) {    // grid=SCAN_BLOCKS, block=256
    __shared__ int sh[256];
    __shared__ int bs[256];
    int tid = threadIdx.x;
    int i = blockIdx.x * 256 + tid;
    int c = (i < n) ? g_cnt[i] : 0;
    sh[tid] = c;
    bs[tid] = (tid < SCAN_BLOCKS) ? g_bsum[tid] : 0;
    __syncthreads();
    for (int o = 1; o < 256; o <<= 1) {
        int u  = (tid >= o) ? sh[tid - o] : 0;
        int u2 = (tid >= o) ? bs[tid - o] : 0;
        __syncthreads();
        sh[tid] += u;
        bs[tid] += u2;
        __syncthreads();
    }
    int off = (blockIdx.x == 0) ? 0 : bs[blockIdx.x - 1];
    if (i < n) {
        g_rowstart[i] = off + sh[tid] - c;        // exclusive prefix
        g_dinv[i] = rsqrtf((float)c + 1.0f);
    }
    if (i == n - 1) g_rowstart[n] = off + sh[tid];
}

// fill: atomically bump rowstart[d]; afterwards rowstart[v] == end(v). 8 edges/thread.
__global__ void k_fill(const int* __restrict__ ei, int E) {
    int t = blockIdx.x * blockDim.x + threadIdx.x;
    if (t * 8 >= E) return;
    const int4* sp = (const int4*)ei;
    const int4* dp = (const int4*)(ei + E);
    int4 s0 = sp[t * 2], s1 = sp[t * 2 + 1];
    int4 d0 = dp[t * 2], d1 = dp[t * 2 + 1];
    int p0 = atomicAdd(&g_rowstart[d0.x], 1);
    int p1 = atomicAdd(&g_rowstart[d0.y], 1);
    int p2 = atomicAdd(&g_rowstart[d0.z], 1);
    int p3 = atomicAdd(&g_rowstart[d0.w], 1);
    int p4 = atomicAdd(&g_rowstart[d1.x], 1);
    int p5 = atomicAdd(&g_rowstart[d1.y], 1);
    int p6 = atomicAdd(&g_rowstart[d1.z], 1);
    int p7 = atomicAdd(&g_rowstart[d1.w], 1);
    g_srcs[p0] = s0.x;
    g_srcs[p1] = s0.y;
    g_srcs[p2] = s0.z;
    g_srcs[p3] = s0.w;
    g_srcs[p4] = s1.x;
    g_srcs[p5] = s1.y;
    g_srcs[p6] = s1.z;
    g_srcs[p7] = s1.w;
}

// ---------------- helpers for tf32 tensor-core GEMM ----------------
__device__ __forceinline__ uint32_t f2tf32(float f) {
    uint32_t r;
    asm("cvt.rna.tf32.f32 %0, %1;" : "=r"(r) : "f"(f));
    return r;
}

__device__ __forceinline__ void mma_tf32(float c[4],
                                         uint32_t a0, uint32_t a1, uint32_t a2, uint32_t a3,
                                         uint32_t b0, uint32_t b1) {
    asm volatile(
        "mma.sync.aligned.m16n8k8.row.col.f32.tf32.tf32.f32 "
        "{%0,%1,%2,%3}, {%4,%5,%6,%7}, {%8,%9}, {%0,%1,%2,%3};"
        : "+f"(c[0]), "+f"(c[1]), "+f"(c[2]), "+f"(c[3])
        : "r"(a0), "r"(a1), "r"(a2), "r"(a3), "r"(b0), "r"(b1));
}

// ---------------- GEMM (tensor core tf32): g_hh[row] = A[row] @ W (raw) ----------------
// BM=128, BN=64, BK=32. 256 threads = 8 warps (4m x 2n); warp tile 32x32.
__global__ void __launch_bounds__(256)
k_gemm_tc(const float* __restrict__ Ain, const float* __restrict__ W,
          int N, int Fout, int useZ) {
    const int K = 128;
    const float* A = useZ ? (const float*)g_z : Ain;

    __shared__ uint32_t As[128][36];   // [m][k], pad 4 -> conflict-free
    __shared__ uint32_t Ws[32][68];    // [k][n], pad 4 -> conflict-free

    int tid  = threadIdx.x;
    int warp = tid >> 5, lane = tid & 31;
    int wm = warp >> 1, wn = warp & 1;
    int rb = blockIdx.x * 128, cb = blockIdx.y * 64;
    int grp = lane >> 2, tg = lane & 3;

    float c[2][4][4] = {};   // [m-frag][n-frag][c0..c3]

    for (int k0 = 0; k0 < K; k0 += 32) {
#pragma unroll
        for (int i = 0; i < 4; i++) {
            int idx = tid + i * 256;
            int row = idx >> 3;
            int cc  = (idx & 7) * 4;
            float4 v = make_float4(0.f, 0.f, 0.f, 0.f);
            if (rb + row < N) v = *(const float4*)(A + (size_t)(rb + row) * K + k0 + cc);
            As[row][cc + 0] = f2tf32(v.x);
            As[row][cc + 1] = f2tf32(v.y);
            As[row][cc + 2] = f2tf32(v.z);
            As[row][cc + 3] = f2tf32(v.w);
        }
#pragma unroll
        for (int i = 0; i < 2; i++) {
            int idx = tid + i * 256;
            int kk = idx >> 4;
            int cc = (idx & 15) * 4;
            float4 v = *(const float4*)(W + (size_t)(k0 + kk) * Fout + cb + cc);
            Ws[kk][cc + 0] = f2tf32(v.x);
            Ws[kk][cc + 1] = f2tf32(v.y);
            Ws[kk][cc + 2] = f2tf32(v.z);
            Ws[kk][cc + 3] = f2tf32(v.w);
        }
        __syncthreads();

#pragma unroll
        for (int ks = 0; ks < 4; ks++) {
            int kb = ks * 8;
            uint32_t a[2][4], b[4][2];
#pragma unroll
            for (int mi = 0; mi < 2; mi++) {
                int r0 = wm * 32 + mi * 16 + grp;
                a[mi][0] = As[r0][kb + tg];
                a[mi][1] = As[r0 + 8][kb + tg];
                a[mi][2] = As[r0][kb + tg + 4];
                a[mi][3] = As[r0 + 8][kb + tg + 4];
            }
#pragma unroll
            for (int ni = 0; ni < 4; ni++) {
                int n0 = wn * 32 + ni * 8 + grp;
                b[ni][0] = Ws[kb + tg][n0];
                b[ni][1] = Ws[kb + tg + 4][n0];
            }
#pragma unroll
            for (int mi = 0; mi < 2; mi++)
#pragma unroll
                for (int ni = 0; ni < 4; ni++)
                    mma_tf32(c[mi][ni], a[mi][0], a[mi][1], a[mi][2], a[mi][3],
                             b[ni][0], b[ni][1]);
        }
        __syncthreads();
    }

#pragma unroll
    for (int mi = 0; mi < 2; mi++) {
#pragma unroll
        for (int half = 0; half < 2; half++) {
            int row = rb + wm * 32 + mi * 16 + grp + half * 8;
            if (row < N) {
#pragma unroll
                for (int ni = 0; ni < 4; ni++) {
                    int col = cb + wn * 32 + ni * 8 + tg * 2;
                    float2 o = make_float2(c[mi][ni][half * 2 + 0],
                                           c[mi][ni][half * 2 + 1]);
                    *(float2*)(g_hh + (size_t)row * Fout + col) = o;
                }
            }
        }
    }
}

// ---------------- Aggregation ----------------
// out[v] = relu?( dinv[v] * ( Σ_s dinv[s]*h[s] + dinv[v]*h[v] ) + b )
// Neighbor range of v is [rowstart[v-1], rowstart[v]) (rowstart holds ENDs after k_fill).
template <int VEC>   // VEC=4 -> F=128, VEC=2 -> F=64
__global__ void k_agg(const float* __restrict__ bias, int N, int F, int relu, int toZ) {
    int warp = (blockIdx.x * blockDim.x + threadIdx.x) >> 5;
    int lane = threadIdx.x & 31;
    if (warp >= N) return;
    int v = warp;
    int fo = lane * VEC;
    const float* __restrict__ hh = g_hh;

    float dvv = __ldg(&g_dinv[v]);
    float acc[VEC];
    {
        const float* hv = hh + (size_t)v * F + fo;
        if (VEC == 4) {
            float4 t = *(const float4*)hv;
            acc[0] = t.x * dvv; acc[1] = t.y * dvv; acc[2] = t.z * dvv; acc[3] = t.w * dvv;
        } else {
            float2 t = *(const float2*)hv;
            acc[0] = t.x * dvv; acc[1] = t.y * dvv;
        }
    }
    int e1 = __ldg(&g_rowstart[v]);
    int e0 = (v == 0) ? 0 : __ldg(&g_rowstart[v - 1]);

    int i = e0;
    for (; i + 8 <= e1; i += 8) {
        int s[8];
        float dv[8];
#pragma unroll
        for (int j = 0; j < 8; j++) s[j] = __ldg(&g_srcs[i + j]);
#pragma unroll
        for (int j = 0; j < 8; j++) dv[j] = __ldg(&g_dinv[s[j]]);
#pragma unroll
        for (int j = 0; j < 8; j++) {
            const float* hs = hh + (size_t)s[j] * F + fo;
            if (VEC == 4) {
                float4 t = *(const float4*)hs;
                acc[0] = fmaf(t.x, dv[j], acc[0]);
                acc[1] = fmaf(t.y, dv[j], acc[1]);
                acc[2] = fmaf(t.z, dv[j], acc[2]);
                acc[3] = fmaf(t.w, dv[j], acc[3]);
            } else {
                float2 t = *(const float2*)hs;
                acc[0] = fmaf(t.x, dv[j], acc[0]);
                acc[1] = fmaf(t.y, dv[j], acc[1]);
            }
        }
    }
    for (; i < e1; i++) {
        int s = __ldg(&g_srcs[i]);
        float dv = __ldg(&g_dinv[s]);
        const float* hs = hh + (size_t)s * F + fo;
        if (VEC == 4) {
            float4 t = *(const float4*)hs;
            acc[0] = fmaf(t.x, dv, acc[0]);
            acc[1] = fmaf(t.y, dv, acc[1]);
            acc[2] = fmaf(t.z, dv, acc[2]);
            acc[3] = fmaf(t.w, dv, acc[3]);
        } else {
            float2 t = *(const float2*)hs;
            acc[0] = fmaf(t.x, dv, acc[0]);
            acc[1] = fmaf(t.y, dv, acc[1]);
        }
    }

    float o[VEC];
#pragma unroll
    for (int k = 0; k < VEC; k++) {
        float val = fmaf(acc[k], dvv, bias[fo + k]);
        if (relu) val = fmaxf(val, 0.f);
        o[k] = val;
    }
    float* op = (toZ ? g_z : g_zout) + (size_t)v * F + fo;
    if (VEC == 4) *(float4*)op = make_float4(o[0], o[1], o[2], o[3]);
    else          *(float2*)op = make_float2(o[0], o[1]);
}

// ---------------- Decode: out[j] = dot(zout[a], zout[b]) over 64 dims ----------------
__global__ void k_decode(const int* __restrict__ eli, float* __restrict__ out, int L) {
    int warp = (blockIdx.x * blockDim.x + threadIdx.x) >> 5;
    int lane = threadIdx.x & 31;
    if (warp >= L) return;
    int a = eli[warp];
    int b = eli[(size_t)L + warp];
    float2 za = *(const float2*)(g_zout + (size_t)a * 64 + lane * 2);
    float2 zb = *(const float2*)(g_zout + (size_t)b * 64 + lane * 2);
    float p = za.x * zb.x + za.y * zb.y;
#pragma unroll
    for (int off = 16; off > 0; off >>= 1)
        p += __shfl_xor_sync(0xffffffff, p, off);
    if (lane == 0) out[warp] = p;
}

static inline int aggGrid(int nNodes) { return (nNodes * 32 + 255) / 256; }

// ---------------- launch ----------------
extern "C" void kernel_launch(void* const* d_in, const int* in_sizes, int n_in,
                              void* d_out, int out_size) {
    const float* x   = (const float*)d_in[0];
    const int*   ei  = (const int*)d_in[1];    // int32 (JAX x64 disabled)
    const int*   eli = (const int*)d_in[2];
    const float* W1  = (const float*)d_in[3];
    const float* b1  = (const float*)d_in[4];
    const float* W2  = (const float*)d_in[5];
    const float* b2  = (const float*)d_in[6];
    const float* W3  = (const float*)d_in[7];
    const float* b3  = (const float*)d_in[8];
    float* out = (float*)d_out;

    // single side stream + 4 events (footprint stays under the harness's
    // teardown memory guard — two streams tripped it in round 10)
    cudaStream_t s2;
    cudaEvent_t ev0, evG1, evScan, evZero;
    cudaStreamCreateWithFlags(&s2, cudaStreamNonBlocking);
    cudaEventCreateWithFlags(&ev0,    cudaEventDisableTiming);
    cudaEventCreateWithFlags(&evG1,   cudaEventDisableTiming);
    cudaEventCreateWithFlags(&evScan, cudaEventDisableTiming);
    cudaEventCreateWithFlags(&evZero, cudaEventDisableTiming);

    // fork: GEMM-1 -> g_hh (independent of CSR) runs concurrently with CSR build
    cudaEventRecord(ev0, 0);
    cudaStreamWaitEvent(s2, ev0, 0);
    k_gemm_tc<<<dim3((NNODES + 127) / 128, FHID / 64), 256, 0, s2>>>(x, W1, NNODES, FHID, 0);
    cudaEventRecord(evG1, s2);

    // CSR build on main stream (g_cnt is zero: module init on first call,
    // deferred zeroing below on all subsequent calls/replays)
    k_count<<<(NEDGES / 8 + 255) / 256, 256>>>(ei, NEDGES);
    k_scanA<<<SCAN_BLOCKS, 256>>>(NNODES);
    k_scanC<<<SCAN_BLOCKS, 256>>>(NNODES);
    cudaEventRecord(evScan, 0);               // last reader of g_cnt done
    k_fill<<<(NEDGES / 8 + 255) / 256, 256>>>(ei, NEDGES);

    // deferred g_cnt zeroing on s2 (after gemm1, after scanC) — off the critical path
    cudaStreamWaitEvent(s2, evScan, 0);
    k_zero<<<(NNODES + 255) / 256, 256, 0, s2>>>(NNODES);
    cudaEventRecord(evZero, s2);

    cudaStreamWaitEvent(0, evG1, 0);          // join gemm1

    // ---- layer 1 agg -> z (relu) ----
    k_agg<4><<<aggGrid(NNODES), 256>>>(b1, NNODES, 128, 1, 1);
    // ---- layer 2 ----
    k_gemm_tc<<<dim3((NNODES + 127) / 128, FHID / 64), 256>>>(nullptr, W2, NNODES, FHID, 1);
    k_agg<4><<<aggGrid(NNODES), 256>>>(b2, NNODES, 128, 1, 1);
    // ---- layer 3 ----
    k_gemm_tc<<<dim3((NNODES + 127) / 128, FOUT / 64), 256>>>(nullptr, W3, NNODES, FOUT, 1);
    k_agg<2><<<aggGrid(NNODES), 256>>>(b3, NNODES, 64, 0, 0);

    // join deferred zero (must complete within this graph) + decode
    cudaStreamWaitEvent(0, evZero, 0);
    k_decode<<<(NLBL * 32 + 255) / 256, 256>>>(eli, out, NLBL);
}

// round 15
// speedup vs baseline: 1.0958x; 1.0110x over previous
#include <cuda_runtime.h>
#include <cstdint>

#define NNODES 50000
#define NEDGES 800000
#define NLBL   100000
#define FIN    128
#define FHID   128
#define FOUT   64

#define SCAN_BLOCKS 196   // 196*256 = 50176 >= NNODES

// ---------------- device scratch (static, no runtime allocation) ----------------
__device__ int   g_cnt[NNODES];            // zero at module load; re-zeroed off-critical-path each call
__device__ int   g_bsum[SCAN_BLOCKS];
__device__ int   g_rowstart[NNODES + 1];   // after k_fill: g_rowstart[v] = END of v's range
__device__ float g_dinv[NNODES];
__device__ int   g_srcs[NEDGES];
__device__ __align__(16) float g_hh[(size_t)NNODES * 128];    // raw GEMM out (h = A @ W)
__device__ __align__(16) float g_z[(size_t)NNODES * 128];     // layer activation
__device__ __align__(16) float g_zout[(size_t)NNODES * 64];   // final embeddings

// ---------------- CSR build ----------------
__global__ void k_zero(int n) {
    int i = blockIdx.x * blockDim.x + threadIdx.x;
    if (i < n) g_cnt[i] = 0;
}

// 8 edges per thread: 8 independent atomic chains in flight
__global__ void k_count(const int* __restrict__ ei, int E) {
    int t = blockIdx.x * blockDim.x + threadIdx.x;
    if (t * 8 >= E) return;
    const int4* dp = (const int4*)(ei + E);
    int4 d0 = dp[t * 2];
    int4 d1 = dp[t * 2 + 1];
    atomicAdd(&g_cnt[d0.x], 1);
    atomicAdd(&g_cnt[d0.y], 1);
    atomicAdd(&g_cnt[d0.z], 1);
    atomicAdd(&g_cnt[d0.w], 1);
    atomicAdd(&g_cnt[d1.x], 1);
    atomicAdd(&g_cnt[d1.y], 1);
    atomicAdd(&g_cnt[d1.z], 1);
    atomicAdd(&g_cnt[d1.w], 1);
}

// ---- two-phase parallel scan over g_cnt ----
__global__ void k_scanA(int n) {    // grid=SCAN_BLOCKS, block=256: block sums
    int tid = threadIdx.x;
    int i = blockIdx.x * 256 + tid;
    int c = (i < n) ? g_cnt[i] : 0;
    __shared__ int ws[8];
    int s = c;
#pragma unroll
    for (int o = 16; o; o >>= 1) s += __shfl_xor_sync(0xffffffffu, s, o);
    if ((tid & 31) == 0) ws[tid >> 5] = s;
    __syncthreads();
    if (tid < 8) {
        int t = ws[tid];
#pragma unroll
        for (int o = 4; o; o >>= 1) t += __shfl_xor_sync(0xffu, t, o);
        if (tid == 0) g_bsum[blockIdx.x] = t;
    }
}

// local scan + redundant per-block scan of the 196 block sums (no separate phase-B launch)
__global__ void k_scanC(int n) {    // grid=SCAN_BLOCKS, block=256
    __shared__ int sh[256];
    __shared__ int bs[256];
    int tid = threadIdx.x;
    int i = blockIdx.x * 256 + tid;
    int c = (i < n) ? g_cnt[i] : 0;
    sh[tid] = c;
    bs[tid] = (tid < SCAN_BLOCKS) ? g_bsum[tid] : 0;
    __syncthreads();
    for (int o = 1; o < 256; o <<= 1) {
        int u  = (tid >= o) ? sh[tid - o] : 0;
        int u2 = (tid >= o) ? bs[tid - o] : 0;
        __syncthreads();
        sh[tid] += u;
        bs[tid] += u2;
        __syncthreads();
    }
    int off = (blockIdx.x == 0) ? 0 : bs[blockIdx.x - 1];
    if (i < n) {
        g_rowstart[i] = off + sh[tid] - c;        // exclusive prefix
        g_dinv[i] = rsqrtf((float)c + 1.0f);
    }
    if (i == n - 1) g_rowstart[n] = off + sh[tid];
}

// fill: atomically bump rowstart[d]; afterwards rowstart[v] == end(v). 8 edges/thread.
__global__ void k_fill(const int* __restrict__ ei, int E) {
    int t = blockIdx.x * blockDim.x + threadIdx.x;
    if (t * 8 >= E) return;
    const int4* sp = (const int4*)ei;
    const int4* dp = (const int4*)(ei + E);
    int4 s0 = sp[t * 2], s1 = sp[t * 2 + 1];
    int4 d0 = dp[t * 2], d1 = dp[t * 2 + 1];
    int p0 = atomicAdd(&g_rowstart[d0.x], 1);
    int p1 = atomicAdd(&g_rowstart[d0.y], 1);
    int p2 = atomicAdd(&g_rowstart[d0.z], 1);
    int p3 = atomicAdd(&g_rowstart[d0.w], 1);
    int p4 = atomicAdd(&g_rowstart[d1.x], 1);
    int p5 = atomicAdd(&g_rowstart[d1.y], 1);
    int p6 = atomicAdd(&g_rowstart[d1.z], 1);
    int p7 = atomicAdd(&g_rowstart[d1.w], 1);
    g_srcs[p0] = s0.x;
    g_srcs[p1] = s0.y;
    g_srcs[p2] = s0.z;
    g_srcs[p3] = s0.w;
    g_srcs[p4] = s1.x;
    g_srcs[p5] = s1.y;
    g_srcs[p6] = s1.z;
    g_srcs[p7] = s1.w;
}

// ---------------- helpers for tf32 tensor-core GEMM ----------------
__device__ __forceinline__ uint32_t f2tf32(float f) {
    uint32_t r;
    asm("cvt.rna.tf32.f32 %0, %1;" : "=r"(r) : "f"(f));
    return r;
}

__device__ __forceinline__ void mma_tf32(float c[4],
                                         uint32_t a0, uint32_t a1, uint32_t a2, uint32_t a3,
                                         uint32_t b0, uint32_t b1) {
    asm volatile(
        "mma.sync.aligned.m16n8k8.row.col.f32.tf32.tf32.f32 "
        "{%0,%1,%2,%3}, {%4,%5,%6,%7}, {%8,%9}, {%0,%1,%2,%3};"
        : "+f"(c[0]), "+f"(c[1]), "+f"(c[2]), "+f"(c[3])
        : "r"(a0), "r"(a1), "r"(a2), "r"(a3), "r"(b0), "r"(b1));
}

// ---------------- GEMM (tensor core tf32): g_hh[row] = A[row] @ W (raw) ----------------
// BM=128, BN=64, BK=32. 256 threads = 8 warps (4m x 2n); warp tile 32x32.
__global__ void __launch_bounds__(256)
k_gemm_tc(const float* __restrict__ Ain, const float* __restrict__ W,
          int N, int Fout, int useZ) {
    const int K = 128;
    const float* A = useZ ? (const float*)g_z : Ain;

    __shared__ uint32_t As[128][36];   // [m][k], pad 4 -> conflict-free
    __shared__ uint32_t Ws[32][68];    // [k][n], pad 4 -> conflict-free

    int tid  = threadIdx.x;
    int warp = tid >> 5, lane = tid & 31;
    int wm = warp >> 1, wn = warp & 1;
    int rb = blockIdx.x * 128, cb = blockIdx.y * 64;
    int grp = lane >> 2, tg = lane & 3;

    float c[2][4][4] = {};   // [m-frag][n-frag][c0..c3]

    for (int k0 = 0; k0 < K; k0 += 32) {
#pragma unroll
        for (int i = 0; i < 4; i++) {
            int idx = tid + i * 256;
            int row = idx >> 3;
            int cc  = (idx & 7) * 4;
            float4 v = make_float4(0.f, 0.f, 0.f, 0.f);
            if (rb + row < N) v = *(const float4*)(A + (size_t)(rb + row) * K + k0 + cc);
            As[row][cc + 0] = f2tf32(v.x);
            As[row][cc + 1] = f2tf32(v.y);
            As[row][cc + 2] = f2tf32(v.z);
            As[row][cc + 3] = f2tf32(v.w);
        }
#pragma unroll
        for (int i = 0; i < 2; i++) {
            int idx = tid + i * 256;
            int kk = idx >> 4;
            int cc = (idx & 15) * 4;
            float4 v = *(const float4*)(W + (size_t)(k0 + kk) * Fout + cb + cc);
            Ws[kk][cc + 0] = f2tf32(v.x);
            Ws[kk][cc + 1] = f2tf32(v.y);
            Ws[kk][cc + 2] = f2tf32(v.z);
            Ws[kk][cc + 3] = f2tf32(v.w);
        }
        __syncthreads();

#pragma unroll
        for (int ks = 0; ks < 4; ks++) {
            int kb = ks * 8;
            uint32_t a[2][4], b[4][2];
#pragma unroll
            for (int mi = 0; mi < 2; mi++) {
                int r0 = wm * 32 + mi * 16 + grp;
                a[mi][0] = As[r0][kb + tg];
                a[mi][1] = As[r0 + 8][kb + tg];
                a[mi][2] = As[r0][kb + tg + 4];
                a[mi][3] = As[r0 + 8][kb + tg + 4];
            }
#pragma unroll
            for (int ni = 0; ni < 4; ni++) {
                int n0 = wn * 32 + ni * 8 + grp;
                b[ni][0] = Ws[kb + tg][n0];
                b[ni][1] = Ws[kb + tg + 4][n0];
            }
#pragma unroll
            for (int mi = 0; mi < 2; mi++)
#pragma unroll
                for (int ni = 0; ni < 4; ni++)
                    mma_tf32(c[mi][ni], a[mi][0], a[mi][1], a[mi][2], a[mi][3],
                             b[ni][0], b[ni][1]);
        }
        __syncthreads();
    }

#pragma unroll
    for (int mi = 0; mi < 2; mi++) {
#pragma unroll
        for (int half = 0; half < 2; half++) {
            int row = rb + wm * 32 + mi * 16 + grp + half * 8;
            if (row < N) {
#pragma unroll
                for (int ni = 0; ni < 4; ni++) {
                    int col = cb + wn * 32 + ni * 8 + tg * 2;
                    float2 o = make_float2(c[mi][ni][half * 2 + 0],
                                           c[mi][ni][half * 2 + 1]);
                    *(float2*)(g_hh + (size_t)row * Fout + col) = o;
                }
            }
        }
    }
}

// ---------------- Aggregation ----------------
// out[v] = relu?( dinv[v] * ( Σ_s dinv[s]*h[s] + dinv[v]*h[v] ) + b )
// Neighbor range of v is [rowstart[v-1], rowstart[v]) (rowstart holds ENDs after k_fill).
template <int VEC>   // VEC=4 -> F=128, VEC=2 -> F=64
__global__ void k_agg(const float* __restrict__ bias, int N, int F, int relu, int toZ) {
    int warp = (blockIdx.x * blockDim.x + threadIdx.x) >> 5;
    int lane = threadIdx.x & 31;
    if (warp >= N) return;
    int v = warp;
    int fo = lane * VEC;
    const float* __restrict__ hh = g_hh;

    float dvv = __ldg(&g_dinv[v]);
    float acc[VEC];
    {
        const float* hv = hh + (size_t)v * F + fo;
        if (VEC == 4) {
            float4 t = *(const float4*)hv;
            acc[0] = t.x * dvv; acc[1] = t.y * dvv; acc[2] = t.z * dvv; acc[3] = t.w * dvv;
        } else {
            float2 t = *(const float2*)hv;
            acc[0] = t.x * dvv; acc[1] = t.y * dvv;
        }
    }
    int e1 = __ldg(&g_rowstart[v]);
    int e0 = (v == 0) ? 0 : __ldg(&g_rowstart[v - 1]);

    int i = e0;
    // main: 12 independent row loads in flight
    for (; i + 12 <= e1; i += 12) {
        int s[12];
        float dv[12];
#pragma unroll
        for (int j = 0; j < 12; j++) s[j] = __ldg(&g_srcs[i + j]);
#pragma unroll
        for (int j = 0; j < 12; j++) dv[j] = __ldg(&g_dinv[s[j]]);
#pragma unroll
        for (int j = 0; j < 12; j++) {
            const float* hs = hh + (size_t)s[j] * F + fo;
            if (VEC == 4) {
                float4 t = *(const float4*)hs;
                acc[0] = fmaf(t.x, dv[j], acc[0]);
                acc[1] = fmaf(t.y, dv[j], acc[1]);
                acc[2] = fmaf(t.z, dv[j], acc[2]);
                acc[3] = fmaf(t.w, dv[j], acc[3]);
            } else {
                float2 t = *(const float2*)hs;
                acc[0] = fmaf(t.x, dv[j], acc[0]);
                acc[1] = fmaf(t.y, dv[j], acc[1]);
            }
        }
    }
    // mid tail: 4 in flight
    for (; i + 4 <= e1; i += 4) {
        int s[4];
        float dv[4];
#pragma unroll
        for (int j = 0; j < 4; j++) s[j] = __ldg(&g_srcs[i + j]);
#pragma unroll
        for (int j = 0; j < 4; j++) dv[j] = __ldg(&g_dinv[s[j]]);
#pragma unroll
        for (int j = 0; j < 4; j++) {
            const float* hs = hh + (size_t)s[j] * F + fo;
            if (VEC == 4) {
                float4 t = *(const float4*)hs;
                acc[0] = fmaf(t.x, dv[j], acc[0]);
                acc[1] = fmaf(t.y, dv[j], acc[1]);
                acc[2] = fmaf(t.z, dv[j], acc[2]);
                acc[3] = fmaf(t.w, dv[j], acc[3]);
            } else {
                float2 t = *(const float2*)hs;
                acc[0] = fmaf(t.x, dv[j], acc[0]);
                acc[1] = fmaf(t.y, dv[j], acc[1]);
            }
        }
    }
    // scalar tail (<=3 iterations)
    for (; i < e1; i++) {
        int s = __ldg(&g_srcs[i]);
        float dv = __ldg(&g_dinv[s]);
        const float* hs = hh + (size_t)s * F + fo;
        if (VEC == 4) {
            float4 t = *(const float4*)hs;
            acc[0] = fmaf(t.x, dv, acc[0]);
            acc[1] = fmaf(t.y, dv, acc[1]);
            acc[2] = fmaf(t.z, dv, acc[2]);
            acc[3] = fmaf(t.w, dv, acc[3]);
        } else {
            float2 t = *(const float2*)hs;
            acc[0] = fmaf(t.x, dv, acc[0]);
            acc[1] = fmaf(t.y, dv, acc[1]);
        }
    }

    float o[VEC];
#pragma unroll
    for (int k = 0; k < VEC; k++) {
        float val = fmaf(acc[k], dvv, bias[fo + k]);
        if (relu) val = fmaxf(val, 0.f);
        o[k] = val;
    }
    float* op = (toZ ? g_z : g_zout) + (size_t)v * F + fo;
    if (VEC == 4) *(float4*)op = make_float4(o[0], o[1], o[2], o[3]);
    else          *(float2*)op = make_float2(o[0], o[1]);
}

// ---------------- Decode: out[j] = dot(zout[a], zout[b]) over 64 dims ----------------
__global__ void k_decode(const int* __restrict__ eli, float* __restrict__ out, int L) {
    int warp = (blockIdx.x * blockDim.x + threadIdx.x) >> 5;
    int lane = threadIdx.x & 31;
    if (warp >= L) return;
    int a = eli[warp];
    int b = eli[(size_t)L + warp];
    float2 za = *(const float2*)(g_zout + (size_t)a * 64 + lane * 2);
    float2 zb = *(const float2*)(g_zout + (size_t)b * 64 + lane * 2);
    float p = za.x * zb.x + za.y * zb.y;
#pragma unroll
    for (int off = 16; off > 0; off >>= 1)
        p += __shfl_xor_sync(0xffffffff, p, off);
    if (lane == 0) out[warp] = p;
}

static inline int aggGrid(int nNodes) { return (nNodes * 32 + 255) / 256; }

// ---------------- launch ----------------
extern "C" void kernel_launch(void* const* d_in, const int* in_sizes, int n_in,
                              void* d_out, int out_size) {
    const float* x   = (const float*)d_in[0];
    const int*   ei  = (const int*)d_in[1];    // int32 (JAX x64 disabled)
    const int*   eli = (const int*)d_in[2];
    const float* W1  = (const float*)d_in[3];
    const float* b1  = (const float*)d_in[4];
    const float* W2  = (const float*)d_in[5];
    const float* b2  = (const float*)d_in[6];
    const float* W3  = (const float*)d_in[7];
    const float* b3  = (const float*)d_in[8];
    float* out = (float*)d_out;

    // single side stream + 4 events (footprint stays under the harness's
    // teardown memory guard — two streams tripped it in round 10)
    cudaStream_t s2;
    cudaEvent_t ev0, evG1, evScan, evZero;
    cudaStreamCreateWithFlags(&s2, cudaStreamNonBlocking);
    cudaEventCreateWithFlags(&ev0,    cudaEventDisableTiming);
    cudaEventCreateWithFlags(&evG1,   cudaEventDisableTiming);
    cudaEventCreateWithFlags(&evScan, cudaEventDisableTiming);
    cudaEventCreateWithFlags(&evZero, cudaEventDisableTiming);

    // fork: GEMM-1 -> g_hh (independent of CSR) runs concurrently with CSR build
    cudaEventRecord(ev0, 0);
    cudaStreamWaitEvent(s2, ev0, 0);
    k_gemm_tc<<<dim3((NNODES + 127) / 128, FHID / 64), 256, 0, s2>>>(x, W1, NNODES, FHID, 0);
    cudaEventRecord(evG1, s2);

    // CSR build on main stream (g_cnt is zero: module init on first call,
    // deferred zeroing below on all subsequent calls/replays)
    k_count<<<(NEDGES / 8 + 255) / 256, 256>>>(ei, NEDGES);
    k_scanA<<<SCAN_BLOCKS, 256>>>(NNODES);
    k_scanC<<<SCAN_BLOCKS, 256>>>(NNODES);
    cudaEventRecord(evScan, 0);               // last reader of g_cnt done
    k_fill<<<(NEDGES / 8 + 255) / 256, 256>>>(ei, NEDGES);

    // deferred g_cnt zeroing on s2 (after gemm1, after scanC) — off the critical path
    cudaStreamWaitEvent(s2, evScan, 0);
    k_zero<<<(NNODES + 255) / 256, 256, 0, s2>>>(NNODES);
    cudaEventRecord(evZero, s2);

    cudaStreamWaitEvent(0, evG1, 0);          // join gemm1

    // ---- layer 1 agg -> z (relu) ----
    k_agg<4><<<aggGrid(NNODES), 256>>>(b1, NNODES, 128, 1, 1);
    // ---- layer 2 ----
    k_gemm_tc<<<dim3((NNODES + 127) / 128, FHID / 64), 256>>>(nullptr, W2, NNODES, FHID, 1);
    k_agg<4><<<aggGrid(NNODES), 256>>>(b2, NNODES, 128, 1, 1);
    // ---- layer 3 ----
    k_gemm_tc<<<dim3((NNODES + 127) / 128, FOUT / 64), 256>>>(nullptr, W3, NNODES, FOUT, 1);
    k_agg<2><<<aggGrid(NNODES), 256>>>(b3, NNODES, 64, 0, 0);

    // join deferred zero (must complete within this graph) + decode
    cudaStreamWaitEvent(0, evZero, 0);
    k_decode<<<(NLBL * 32 + 255) / 256, 256>>>(eli, out, NLBL);
}

// round 16
// speedup vs baseline: 1.1329x; 1.0339x over previous
#include <cuda_runtime.h>
#include <cstdint>

#define NNODES 50000
#define NEDGES 800000
#define NLBL   100000
#define FIN    128
#define FHID   128
#define FOUT   64

#define SCAN_BLOCKS 196   // 196*256 = 50176 >= NNODES

// ---------------- device scratch (static, no runtime allocation) ----------------
__device__ int   g_cnt[NNODES];            // zero at module load; re-zeroed off-critical-path each call
__device__ int   g_bsum[SCAN_BLOCKS];
__device__ int   g_rowstart[NNODES + 1];   // after k_fill: g_rowstart[v] = END of v's range
__device__ float g_dinv[NNODES];
__device__ int   g_srcs[NEDGES];
__device__ __align__(16) float g_hh[(size_t)NNODES * 128];    // raw GEMM out (h = A @ W)
__device__ __align__(16) float g_z[(size_t)NNODES * 128];     // layer activation
__device__ __align__(16) float g_zout[(size_t)NNODES * 64];   // final embeddings

// ---------------- CSR build ----------------
__global__ void k_zero(int n) {
    int i = blockIdx.x * blockDim.x + threadIdx.x;
    if (i < n) g_cnt[i] = 0;
}

// 8 edges per thread: 8 independent atomic chains in flight
__global__ void k_count(const int* __restrict__ ei, int E) {
    int t = blockIdx.x * blockDim.x + threadIdx.x;
    if (t * 8 >= E) return;
    const int4* dp = (const int4*)(ei + E);
    int4 d0 = dp[t * 2];
    int4 d1 = dp[t * 2 + 1];
    atomicAdd(&g_cnt[d0.x], 1);
    atomicAdd(&g_cnt[d0.y], 1);
    atomicAdd(&g_cnt[d0.z], 1);
    atomicAdd(&g_cnt[d0.w], 1);
    atomicAdd(&g_cnt[d1.x], 1);
    atomicAdd(&g_cnt[d1.y], 1);
    atomicAdd(&g_cnt[d1.z], 1);
    atomicAdd(&g_cnt[d1.w], 1);
}

// ---- two-phase parallel scan over g_cnt ----
__global__ void k_scanA(int n) {    // grid=SCAN_BLOCKS, block=256: block sums
    int tid = threadIdx.x;
    int i = blockIdx.x * 256 + tid;
    int c = (i < n) ? g_cnt[i] : 0;
    __shared__ int ws[8];
    int s = c;
#pragma unroll
    for (int o = 16; o; o >>= 1) s += __shfl_xor_sync(0xffffffffu, s, o);
    if ((tid & 31) == 0) ws[tid >> 5] = s;
    __syncthreads();
    if (tid < 8) {
        int t = ws[tid];
#pragma unroll
        for (int o = 4; o; o >>= 1) t += __shfl_xor_sync(0xffu, t, o);
        if (tid == 0) g_bsum[blockIdx.x] = t;
    }
}

// local scan + redundant per-block scan of the 196 block sums (no separate phase-B launch)
__global__ void k_scanC(int n) {    // grid=SCAN_BLOCKS, block=256
    __shared__ int sh[256];
    __shared__ int bs[256];
    int tid = threadIdx.x;
    int i = blockIdx.x * 256 + tid;
    int c = (i < n) ? g_cnt[i] : 0;
    sh[tid] = c;
    bs[tid] = (tid < SCAN_BLOCKS) ? g_bsum[tid] : 0;
    __syncthreads();
    for (int o = 1; o < 256; o <<= 1) {
        int u  = (tid >= o) ? sh[tid - o] : 0;
        int u2 = (tid >= o) ? bs[tid - o] : 0;
        __syncthreads();
        sh[tid] += u;
        bs[tid] += u2;
        __syncthreads();
    }
    int off = (blockIdx.x == 0) ? 0 : bs[blockIdx.x - 1];
    if (i < n) {
        g_rowstart[i] = off + sh[tid] - c;        // exclusive prefix
        g_dinv[i] = rsqrtf((float)c + 1.0f);
    }
    if (i == n - 1) g_rowstart[n] = off + sh[tid];
}

// fill: atomically bump rowstart[d]; afterwards rowstart[v] == end(v). 8 edges/thread.
__global__ void k_fill(const int* __restrict__ ei, int E) {
    int t = blockIdx.x * blockDim.x + threadIdx.x;
    if (t * 8 >= E) return;
    const int4* sp = (const int4*)ei;
    const int4* dp = (const int4*)(ei + E);
    int4 s0 = sp[t * 2], s1 = sp[t * 2 + 1];
    int4 d0 = dp[t * 2], d1 = dp[t * 2 + 1];
    int p0 = atomicAdd(&g_rowstart[d0.x], 1);
    int p1 = atomicAdd(&g_rowstart[d0.y], 1);
    int p2 = atomicAdd(&g_rowstart[d0.z], 1);
    int p3 = atomicAdd(&g_rowstart[d0.w], 1);
    int p4 = atomicAdd(&g_rowstart[d1.x], 1);
    int p5 = atomicAdd(&g_rowstart[d1.y], 1);
    int p6 = atomicAdd(&g_rowstart[d1.z], 1);
    int p7 = atomicAdd(&g_rowstart[d1.w], 1);
    g_srcs[p0] = s0.x;
    g_srcs[p1] = s0.y;
    g_srcs[p2] = s0.z;
    g_srcs[p3] = s0.w;
    g_srcs[p4] = s1.x;
    g_srcs[p5] = s1.y;
    g_srcs[p6] = s1.z;
    g_srcs[p7] = s1.w;
}

// ---------------- helpers for tf32 tensor-core GEMM ----------------
__device__ __forceinline__ uint32_t f2tf32(float f) {
    uint32_t r;
    asm("cvt.rna.tf32.f32 %0, %1;" : "=r"(r) : "f"(f));
    return r;
}

__device__ __forceinline__ void mma_tf32(float c[4],
                                         uint32_t a0, uint32_t a1, uint32_t a2, uint32_t a3,
                                         uint32_t b0, uint32_t b1) {
    asm volatile(
        "mma.sync.aligned.m16n8k8.row.col.f32.tf32.tf32.f32 "
        "{%0,%1,%2,%3}, {%4,%5,%6,%7}, {%8,%9}, {%0,%1,%2,%3};"
        : "+f"(c[0]), "+f"(c[1]), "+f"(c[2]), "+f"(c[3])
        : "r"(a0), "r"(a1), "r"(a2), "r"(a3), "r"(b0), "r"(b1));
}

// ---------------- GEMM (tensor core tf32): g_hh[row] = A[row] @ W (raw) ----------------
// BM=128, BN=64, BK=32. 256 threads = 8 warps (4m x 2n); warp tile 32x32.
__global__ void __launch_bounds__(256)
k_gemm_tc(const float* __restrict__ Ain, const float* __restrict__ W,
          int N, int Fout, int useZ) {
    const int K = 128;
    const float* A = useZ ? (const float*)g_z : Ain;

    __shared__ uint32_t As[128][36];   // [m][k], pad 4 -> conflict-free
    __shared__ uint32_t Ws[32][68];    // [k][n], pad 4 -> conflict-free

    int tid  = threadIdx.x;
    int warp = tid >> 5, lane = tid & 31;
    int wm = warp >> 1, wn = warp & 1;
    int rb = blockIdx.x * 128, cb = blockIdx.y * 64;
    int grp = lane >> 2, tg = lane & 3;

    float c[2][4][4] = {};   // [m-frag][n-frag][c0..c3]

    for (int k0 = 0; k0 < K; k0 += 32) {
#pragma unroll
        for (int i = 0; i < 4; i++) {
            int idx = tid + i * 256;
            int row = idx >> 3;
            int cc  = (idx & 7) * 4;
            float4 v = make_float4(0.f, 0.f, 0.f, 0.f);
            if (rb + row < N) v = *(const float4*)(A + (size_t)(rb + row) * K + k0 + cc);
            As[row][cc + 0] = f2tf32(v.x);
            As[row][cc + 1] = f2tf32(v.y);
            As[row][cc + 2] = f2tf32(v.z);
            As[row][cc + 3] = f2tf32(v.w);
        }
#pragma unroll
        for (int i = 0; i < 2; i++) {
            int idx = tid + i * 256;
            int kk = idx >> 4;
            int cc = (idx & 15) * 4;
            float4 v = *(const float4*)(W + (size_t)(k0 + kk) * Fout + cb + cc);
            Ws[kk][cc + 0] = f2tf32(v.x);
            Ws[kk][cc + 1] = f2tf32(v.y);
            Ws[kk][cc + 2] = f2tf32(v.z);
            Ws[kk][cc + 3] = f2tf32(v.w);
        }
        __syncthreads();

#pragma unroll
        for (int ks = 0; ks < 4; ks++) {
            int kb = ks * 8;
            uint32_t a[2][4], b[4][2];
#pragma unroll
            for (int mi = 0; mi < 2; mi++) {
                int r0 = wm * 32 + mi * 16 + grp;
                a[mi][0] = As[r0][kb + tg];
                a[mi][1] = As[r0 + 8][kb + tg];
                a[mi][2] = As[r0][kb + tg + 4];
                a[mi][3] = As[r0 + 8][kb + tg + 4];
            }
#pragma unroll
            for (int ni = 0; ni < 4; ni++) {
                int n0 = wn * 32 + ni * 8 + grp;
                b[ni][0] = Ws[kb + tg][n0];
                b[ni][1] = Ws[kb + tg + 4][n0];
            }
#pragma unroll
            for (int mi = 0; mi < 2; mi++)
#pragma unroll
                for (int ni = 0; ni < 4; ni++)
                    mma_tf32(c[mi][ni], a[mi][0], a[mi][1], a[mi][2], a[mi][3],
                             b[ni][0], b[ni][1]);
        }
        __syncthreads();
    }

#pragma unroll
    for (int mi = 0; mi < 2; mi++) {
#pragma unroll
        for (int half = 0; half < 2; half++) {
            int row = rb + wm * 32 + mi * 16 + grp + half * 8;
            if (row < N) {
#pragma unroll
                for (int ni = 0; ni < 4; ni++) {
                    int col = cb + wn * 32 + ni * 8 + tg * 2;
                    float2 o = make_float2(c[mi][ni][half * 2 + 0],
                                           c[mi][ni][half * 2 + 1]);
                    *(float2*)(g_hh + (size_t)row * Fout + col) = o;
                }
            }
        }
    }
}

// ---------------- Aggregation ----------------
// out[v] = relu?( dinv[v] * ( Σ_s dinv[s]*h[s] + dinv[v]*h[v] ) + b )
// Neighbor range of v is [rowstart[v-1], rowstart[v]) (rowstart holds ENDs after k_fill).
template <int VEC, int B>   // helper: one B-wide pipelined batch starting at i
__device__ __forceinline__ void agg_batch(const float* __restrict__ hh, int i, int fo, int F,
                                          float acc[VEC]) {
    int s[B];
    float dv[B];
#pragma unroll
    for (int j = 0; j < B; j++) s[j] = __ldg(&g_srcs[i + j]);
#pragma unroll
    for (int j = 0; j < B; j++) dv[j] = __ldg(&g_dinv[s[j]]);
#pragma unroll
    for (int j = 0; j < B; j++) {
        const float* hs = hh + (size_t)s[j] * F + fo;
        if (VEC == 4) {
            float4 t = *(const float4*)hs;
            acc[0] = fmaf(t.x, dv[j], acc[0]);
            acc[1] = fmaf(t.y, dv[j], acc[1]);
            acc[2] = fmaf(t.z, dv[j], acc[2]);
            acc[3] = fmaf(t.w, dv[j], acc[3]);
        } else {
            float2 t = *(const float2*)hs;
            acc[0] = fmaf(t.x, dv[j], acc[0]);
            acc[1] = fmaf(t.y, dv[j], acc[1]);
        }
    }
}

template <int VEC>   // VEC=4 -> F=128, VEC=2 -> F=64
__global__ void k_agg(const float* __restrict__ bias, int N, int F, int relu, int toZ) {
    int warp = (blockIdx.x * blockDim.x + threadIdx.x) >> 5;
    int lane = threadIdx.x & 31;
    if (warp >= N) return;
    int v = warp;
    int fo = lane * VEC;
    const float* __restrict__ hh = g_hh;

    float dvv = __ldg(&g_dinv[v]);
    float acc[VEC];
    {
        const float* hv = hh + (size_t)v * F + fo;
        if (VEC == 4) {
            float4 t = *(const float4*)hv;
            acc[0] = t.x * dvv; acc[1] = t.y * dvv; acc[2] = t.z * dvv; acc[3] = t.w * dvv;
        } else {
            float2 t = *(const float2*)hv;
            acc[0] = t.x * dvv; acc[1] = t.y * dvv;
        }
    }
    int e1 = __ldg(&g_rowstart[v]);
    int e0 = (v == 0) ? 0 : __ldg(&g_rowstart[v - 1]);

    int i = e0;
    for (; i + 16 <= e1; i += 16) agg_batch<VEC, 16>(hh, i, fo, F, acc);   // main
    for (; i + 8  <= e1; i += 8)  agg_batch<VEC, 8>(hh, i, fo, F, acc);    // mid tail
    for (; i + 4  <= e1; i += 4)  agg_batch<VEC, 4>(hh, i, fo, F, acc);    // small tail
    for (; i < e1; i++) {                                                   // scalar tail (<=3)
        int s = __ldg(&g_srcs[i]);
        float dv = __ldg(&g_dinv[s]);
        const float* hs = hh + (size_t)s * F + fo;
        if (VEC == 4) {
            float4 t = *(const float4*)hs;
            acc[0] = fmaf(t.x, dv, acc[0]);
            acc[1] = fmaf(t.y, dv, acc[1]);
            acc[2] = fmaf(t.z, dv, acc[2]);
            acc[3] = fmaf(t.w, dv, acc[3]);
        } else {
            float2 t = *(const float2*)hs;
            acc[0] = fmaf(t.x, dv, acc[0]);
            acc[1] = fmaf(t.y, dv, acc[1]);
        }
    }

    float o[VEC];
#pragma unroll
    for (int k = 0; k < VEC; k++) {
        float val = fmaf(acc[k], dvv, bias[fo + k]);
        if (relu) val = fmaxf(val, 0.f);
        o[k] = val;
    }
    float* op = (toZ ? g_z : g_zout) + (size_t)v * F + fo;
    if (VEC == 4) *(float4*)op = make_float4(o[0], o[1], o[2], o[3]);
    else          *(float2*)op = make_float2(o[0], o[1]);
}

// ---------------- Decode: out[j] = dot(zout[a], zout[b]) over 64 dims ----------------
__global__ void k_decode(const int* __restrict__ eli, float* __restrict__ out, int L) {
    int warp = (blockIdx.x * blockDim.x + threadIdx.x) >> 5;
    int lane = threadIdx.x & 31;
    if (warp >= L) return;
    int a = eli[warp];
    int b = eli[(size_t)L + warp];
    float2 za = *(const float2*)(g_zout + (size_t)a * 64 + lane * 2);
    float2 zb = *(const float2*)(g_zout + (size_t)b * 64 + lane * 2);
    float p = za.x * zb.x + za.y * zb.y;
#pragma unroll
    for (int off = 16; off > 0; off >>= 1)
        p += __shfl_xor_sync(0xffffffff, p, off);
    if (lane == 0) out[warp] = p;
}

static inline int aggGrid(int nNodes) { return (nNodes * 32 + 255) / 256; }

// ---------------- launch ----------------
extern "C" void kernel_launch(void* const* d_in, const int* in_sizes, int n_in,
                              void* d_out, int out_size) {
    const float* x   = (const float*)d_in[0];
    const int*   ei  = (const int*)d_in[1];    // int32 (JAX x64 disabled)
    const int*   eli = (const int*)d_in[2];
    const float* W1  = (const float*)d_in[3];
    const float* b1  = (const float*)d_in[4];
    const float* W2  = (const float*)d_in[5];
    const float* b2  = (const float*)d_in[6];
    const float* W3  = (const float*)d_in[7];
    const float* b3  = (const float*)d_in[8];
    float* out = (float*)d_out;

    // single side stream + 4 events (footprint stays under the harness's
    // teardown memory guard — two streams tripped it in round 10)
    cudaStream_t s2;
    cudaEvent_t ev0, evG1, evScan, evZero;
    cudaStreamCreateWithFlags(&s2, cudaStreamNonBlocking);
    cudaEventCreateWithFlags(&ev0,    cudaEventDisableTiming);
    cudaEventCreateWithFlags(&evG1,   cudaEventDisableTiming);
    cudaEventCreateWithFlags(&evScan, cudaEventDisableTiming);
    cudaEventCreateWithFlags(&evZero, cudaEventDisableTiming);

    // fork: GEMM-1 -> g_hh (independent of CSR) runs concurrently with CSR build
    cudaEventRecord(ev0, 0);
    cudaStreamWaitEvent(s2, ev0, 0);
    k_gemm_tc<<<dim3((NNODES + 127) / 128, FHID / 64), 256, 0, s2>>>(x, W1, NNODES, FHID, 0);
    cudaEventRecord(evG1, s2);

    // CSR build on main stream (g_cnt is zero: module init on first call,
    // deferred zeroing below on all subsequent calls/replays)
    k_count<<<(NEDGES / 8 + 255) / 256, 256>>>(ei, NEDGES);
    k_scanA<<<SCAN_BLOCKS, 256>>>(NNODES);
    k_scanC<<<SCAN_BLOCKS, 256>>>(NNODES);
    cudaEventRecord(evScan, 0);               // last reader of g_cnt done
    k_fill<<<(NEDGES / 8 + 255) / 256, 256>>>(ei, NEDGES);

    // deferred g_cnt zeroing on s2 (after gemm1, after scanC) — off the critical path
    cudaStreamWaitEvent(s2, evScan, 0);
    k_zero<<<(NNODES + 255) / 256, 256, 0, s2>>>(NNODES);
    cudaEventRecord(evZero, s2);

    cudaStreamWaitEvent(0, evG1, 0);          // join gemm1

    // ---- layer 1 agg -> z (relu) ----
    k_agg<4><<<aggGrid(NNODES), 256>>>(b1, NNODES, 128, 1, 1);
    // ---- layer 2 ----
    k_gemm_tc<<<dim3((NNODES + 127) / 128, FHID / 64), 256>>>(nullptr, W2, NNODES, FHID, 1);
    k_agg<4><<<aggGrid(NNODES), 256>>>(b2, NNODES, 128, 1, 1);
    // ---- layer 3 ----
    k_gemm_tc<<<dim3((NNODES + 127) / 128, FOUT / 64), 256>>>(nullptr, W3, NNODES, FOUT, 1);
    k_agg<2><<<aggGrid(NNODES), 256>>>(b3, NNODES, 64, 0, 0);

    // join deferred zero (must complete within this graph) + decode
    cudaStreamWaitEvent(0, evZero, 0);
    k_decode<<<(NLBL * 32 + 255) / 256, 256>>>(eli, out, NLBL);
}